// round 1
// baseline (speedup 1.0000x reference)
#include <cuda_runtime.h>

#define CELL_F 30
#define TPB    128
#define PAD    33   // padded cell stride in shared: gcd(33,32)=1 -> conflict-free

__device__ double g_acc;

__global__ void k_zero() { g_acc = 0.0; }

__device__ __forceinline__ float fast_log1pexp(float a) {
    // a = |x| >= 0, returns log(1 + exp(-a))
    return __logf(1.0f + __expf(-a));
}
__device__ __forceinline__ float bce_t(float x, float t) {
    return fmaxf(x, 0.0f) - x * t + fast_log1pexp(fabsf(x));
}
__device__ __forceinline__ float bce_zero(float x) {   // bce(x, 0)
    return fmaxf(x, 0.0f) + fast_log1pexp(fabsf(x));
}
__device__ __forceinline__ float bce_one(float x) {    // bce(x, 1)
    return fmaxf(x, 0.0f) - x + fast_log1pexp(fabsf(x));
}
__device__ __forceinline__ float sigm(float x) {
    return 1.0f / (1.0f + __expf(-x));
}
__device__ __forceinline__ float iou_f(float al, float at, float ar, float ab,
                                       float bl, float bt, float br, float bb,
                                       float area_a, float area_b) {
    float ltx = fmaxf(al, bl), lty = fmaxf(at, bt);
    float rbx = fminf(ar, br), rby = fminf(ab, bb);
    float wx = fmaxf(rbx - ltx, 0.0f), wy = fmaxf(rby - lty, 0.0f);
    float inter = wx * wy;
    return inter / (area_a + area_b - inter + 1e-7f);
}

__global__ void __launch_bounds__(TPB)
k_main(const float* __restrict__ p, const float* __restrict__ g, int ncells) {
    __shared__ float sp[TPB * PAD];
    __shared__ float sg[TPB * PAD];
    const int tid = threadIdx.x;

    long long basef = (long long)blockIdx.x * (TPB * CELL_F);
    long long totf  = (long long)ncells * CELL_F;
    int nf = (int)(((totf - basef) < (long long)(TPB * CELL_F)) ? (totf - basef)
                                                                : (long long)(TPB * CELL_F));
    int n4 = nf >> 2;
    const float4* p4 = reinterpret_cast<const float4*>(p + basef);
    const float4* g4 = reinterpret_cast<const float4*>(g + basef);

    for (int i = tid; i < n4; i += TPB) {
        float4 v = p4[i];
        float4 w = g4[i];
        int f = i * 4;
        float vv[4] = {v.x, v.y, v.z, v.w};
        float ww[4] = {w.x, w.y, w.z, w.w};
        #pragma unroll
        for (int k = 0; k < 4; k++) {
            int ff   = f + k;
            int cell = ff / CELL_F;
            int off  = ff - cell * CELL_F;
            sp[cell * PAD + off] = vv[k];
            sg[cell * PAD + off] = ww[k];
        }
    }
    // scalar tail (only possible on a ragged last block)
    for (int ff = n4 * 4 + tid; ff < nf; ff += TPB) {
        int cell = ff / CELL_F;
        int off  = ff - cell * CELL_F;
        sp[cell * PAD + off] = p[basef + ff];
        sg[cell * PAD + off] = g[basef + ff];
    }
    __syncthreads();

    int cell = blockIdx.x * TPB + tid;
    float loss = 0.0f;
    if (cell < ncells) {
        const float* P = sp + tid * PAD;
        const float* G = sg + tid * PAD;
        float conf_g = G[8];
        if (conf_g > 0.0f) {
            // ---- class BCE (20 classes) ----
            float cls = 0.0f;
            #pragma unroll
            for (int k = 10; k < 30; k++) cls += bce_t(P[k], G[k]);

            // ---- boxes ----
            int ij = cell % 49;
            int r  = ij / 7;
            int c  = ij - r * 7;
            float colf = (float)c, rowf = (float)r;

            float sx0 = sigm(P[0]), sy0 = sigm(P[1]), pw0 = P[2], ph0 = P[3];
            float sx1 = sigm(P[4]), sy1 = sigm(P[5]), pw1 = P[6], ph1 = P[7];
            float gx0 = G[0], gy0 = G[1], gw0 = G[2], gh0 = G[3];
            float gx1 = G[4], gy1 = G[5], gw1 = G[6], gh1 = G[7];

            // LTRB in global [0,1] coords (matches reference arithmetic order)
            float pcx0 = (sx0 + colf) / 7.0f, pcy0 = (sy0 + rowf) / 7.0f;
            float pcx1 = (sx1 + colf) / 7.0f, pcy1 = (sy1 + rowf) / 7.0f;
            float gcx0 = (gx0 + colf) / 7.0f, gcy0 = (gy0 + rowf) / 7.0f;
            float gcx1 = (gx1 + colf) / 7.0f, gcy1 = (gy1 + rowf) / 7.0f;

            float pl0 = pcx0 - pw0 * 0.5f, pt0 = pcy0 - ph0 * 0.5f;
            float pr0 = pcx0 + pw0 * 0.5f, pb0 = pcy0 + ph0 * 0.5f;
            float pl1 = pcx1 - pw1 * 0.5f, pt1 = pcy1 - ph1 * 0.5f;
            float pr1 = pcx1 + pw1 * 0.5f, pb1 = pcy1 + ph1 * 0.5f;
            float gl0 = gcx0 - gw0 * 0.5f, gt0 = gcy0 - gh0 * 0.5f;
            float gr0 = gcx0 + gw0 * 0.5f, gb0 = gcy0 + gh0 * 0.5f;
            float gl1 = gcx1 - gw1 * 0.5f, gt1 = gcy1 - gh1 * 0.5f;
            float gr1 = gcx1 + gw1 * 0.5f, gb1 = gcy1 + gh1 * 0.5f;

            float ap0 = (pr0 - pl0) * (pb0 - pt0);
            float ap1 = (pr1 - pl1) * (pb1 - pt1);
            float ag0 = (gr0 - gl0) * (gb0 - gt0);
            float ag1 = (gr1 - gl1) * (gb1 - gt1);

            float i00 = iou_f(pl0, pt0, pr0, pb0, gl0, gt0, gr0, gb0, ap0, ag0);
            float i10 = iou_f(pl1, pt1, pr1, pb1, gl0, gt0, gr0, gb0, ap1, ag0);
            float i01 = iou_f(pl0, pt0, pr0, pb0, gl1, gt1, gr1, gb1, ap0, ag1);
            float i11 = iou_f(pl1, pt1, pr1, pb1, gl1, gt1, gr1, gb1, ap1, ag1);

            int ind0 = (i10 > i00) ? 1 : 0;   // jnp.argmax: first max wins
            int ind1 = (i11 > i01) ? 1 : 0;

            bool same_g   = (gx0 == gx1) && (gy0 == gy1) && (gw0 == gw1) && (gh0 == gh1);
            bool same_ind = (ind0 == ind1);

            // ---- box loss terms ----
            float sqw0 = sqrtf(fabsf(pw0)), sqh0 = sqrtf(fabsf(ph0));
            float sqw1 = sqrtf(fabsf(pw1)), sqh1 = sqrtf(fabsf(ph1));
            float sgw0 = sqrtf(gw0), sgh0 = sqrtf(gh0);
            float sgw1 = sqrtf(gw1), sgh1 = sqrtf(gh1);

            #define BLOSS(px, py, qw, qh, qx, qy, rw, rh)                         \
                ((px - qx) * (px - qx) + (py - qy) * (py - qy) +                  \
                 (qw - rw) * (qw - rw) + (qh - rh) * (qh - rh))

            float l00 = BLOSS(sx0, sy0, sqw0, sqh0, gx0, gy0, sgw0, sgh0);
            float l10 = BLOSS(sx1, sy1, sqw1, sqh1, gx0, gy0, sgw0, sgh0);
            float l01 = BLOSS(sx0, sy0, sqw0, sqh0, gx1, gy1, sgw1, sgh1);
            float l11 = BLOSS(sx1, sy1, sqw1, sqh1, gx1, gy1, sgw1, sgh1);
            #undef BLOSS

            float lA = ind0 ? l10 : l00;
            float lB = l00 + l11;
            float lC = (ind0 ? l10 : l00) + (ind1 ? l11 : l01);
            float box_cell = same_g ? lA : (same_ind ? lB : lC);

            // ---- positive conf ----
            float pc0 = P[8], pc1 = P[9];
            float confA  = bce_one(ind1 ? pc1 : pc0);
            float confBC = bce_one(pc0) + bce_one(pc1);
            float conf_cell = same_g ? confA : confBC;

            loss = 5.0f * box_cell + conf_cell + cls;
        } else if (conf_g == 0.0f) {
            loss = 0.5f * (bce_zero(P[8]) + bce_zero(P[9]));
        }
    }

    // ---- block reduction ----
    #pragma unroll
    for (int o = 16; o > 0; o >>= 1)
        loss += __shfl_xor_sync(0xFFFFFFFFu, loss, o);
    __shared__ float ws[TPB / 32];
    if ((tid & 31) == 0) ws[tid >> 5] = loss;
    __syncthreads();
    if (tid == 0) {
        float s = 0.0f;
        #pragma unroll
        for (int w = 0; w < TPB / 32; w++) s += ws[w];
        atomicAdd(&g_acc, (double)s);
    }
}

__global__ void k_final(float* out, double inv_batch) {
    *out = (float)(g_acc * inv_batch);
}

extern "C" void kernel_launch(void* const* d_in, const int* in_sizes, int n_in,
                              void* d_out, int out_size) {
    const float* p = (const float*)d_in[0];
    const float* g = (const float*)d_in[1];
    int total  = in_sizes[0];           // B*7*7*30
    int ncells = total / CELL_F;        // B*49
    int batch  = ncells / 49;
    int nb     = (ncells + TPB - 1) / TPB;

    k_zero<<<1, 1>>>();
    k_main<<<nb, TPB>>>(p, g, ncells);
    k_final<<<1, 1>>>((float*)d_out, 1.0 / (double)batch);
}